// round 1
// baseline (speedup 1.0000x reference)
#include <cuda_runtime.h>
#include <math.h>

#define NG 512
#define IMG_H 256
#define IMG_W 256

static __device__ __constant__ const float TANFOV = 0.5f;
#define FXC (256.0f / (2.0f * 0.5f))   /* = 256 */
#define FYC (256.0f / (2.0f * 0.5f))   /* = 256 */
#define LIMX (1.3f * 0.5f)
#define LIMY (1.3f * 0.5f)

// Sorted per-gaussian data, 48 bytes (3 x float4) each:
//  A: px, py, ca, cb    B: cc, op, cr, cg    C: cb(blue), invdepth, pad, pad
struct __align__(16) GData { float4 A, B, C; };
__device__ GData g_sorted[NG];

// ---------------------------------------------------------------------------
// Preprocess: 1 block, 512 threads (one gaussian each) + in-block stable sort
// ---------------------------------------------------------------------------
__global__ void __launch_bounds__(NG)
preprocess_kernel(const float* __restrict__ means3D,
                  const float* __restrict__ opac,
                  const float* __restrict__ colors,
                  const float* __restrict__ scales,
                  const float* __restrict__ rots,
                  const float* __restrict__ view,
                  const float* __restrict__ proj,
                  float* __restrict__ radii_out)
{
    const int i = threadIdx.x;
    __shared__ float sdepth[NG];

    const float m0 = means3D[3 * i + 0];
    const float m1 = means3D[3 * i + 1];
    const float m2 = means3D[3 * i + 2];

    // t = view @ [m,1]
    const float t0 = view[0] * m0 + view[1] * m1 + view[2]  * m2 + view[3];
    const float t1 = view[4] * m0 + view[5] * m1 + view[6]  * m2 + view[7];
    const float t2 = view[8] * m0 + view[9] * m1 + view[10] * m2 + view[11];
    const float depth = t2;
    sdepth[i] = depth;

    // clip = proj @ [m,1]
    const float c0 = proj[0]  * m0 + proj[1]  * m1 + proj[2]  * m2 + proj[3];
    const float c1 = proj[4]  * m0 + proj[5]  * m1 + proj[6]  * m2 + proj[7];
    const float c3 = proj[12] * m0 + proj[13] * m1 + proj[14] * m2 + proj[15];
    const float pw = 1.0f / (c3 + 1e-7f);
    const float px = ((c0 * pw + 1.0f) * (float)IMG_W - 1.0f) * 0.5f;
    const float py = ((c1 * pw + 1.0f) * (float)IMG_H - 1.0f) * 0.5f;

    // quaternion -> rotation
    float qw = rots[4 * i + 0], qx = rots[4 * i + 1],
          qy = rots[4 * i + 2], qz = rots[4 * i + 3];
    const float qn = rsqrtf(qw * qw + qx * qx + qy * qy + qz * qz);
    qw *= qn; qx *= qn; qy *= qn; qz *= qn;
    const float R00 = 1.0f - 2.0f * (qy * qy + qz * qz);
    const float R01 = 2.0f * (qx * qy - qw * qz);
    const float R02 = 2.0f * (qx * qz + qw * qy);
    const float R10 = 2.0f * (qx * qy + qw * qz);
    const float R11 = 1.0f - 2.0f * (qx * qx + qz * qz);
    const float R12 = 2.0f * (qy * qz - qw * qx);
    const float R20 = 2.0f * (qx * qz - qw * qy);
    const float R21 = 2.0f * (qy * qz + qw * qx);
    const float R22 = 1.0f - 2.0f * (qx * qx + qy * qy);

    const float s0 = scales[3 * i + 0];
    const float s1 = scales[3 * i + 1];
    const float s2 = scales[3 * i + 2];

    // M = R * diag(s); cov3d = M M^T
    const float M00 = R00 * s0, M01 = R01 * s1, M02 = R02 * s2;
    const float M10 = R10 * s0, M11 = R11 * s1, M12 = R12 * s2;
    const float M20 = R20 * s0, M21 = R21 * s1, M22 = R22 * s2;
    const float C00 = M00 * M00 + M01 * M01 + M02 * M02;
    const float C01 = M00 * M10 + M01 * M11 + M02 * M12;
    const float C02 = M00 * M20 + M01 * M21 + M02 * M22;
    const float C11 = M10 * M10 + M11 * M11 + M12 * M12;
    const float C12 = M10 * M20 + M11 * M21 + M12 * M22;
    const float C22 = M20 * M20 + M21 * M21 + M22 * M22;

    // EWA Jacobian
    const float tz   = depth;
    const float invz = 1.0f / tz;
    const float tx = fminf(fmaxf(t0 * invz, -LIMX), LIMX) * tz;
    const float ty = fminf(fmaxf(t1 * invz, -LIMY), LIMY) * tz;
    const float J00 = FXC * invz;
    const float J02 = -FXC * tx * invz * invz;
    const float J11 = FYC * invz;
    const float J12 = -FYC * ty * invz * invz;

    // Tm = J(2x3) @ V3(3x3)
    const float V00 = view[0], V01 = view[1], V02 = view[2];
    const float V10 = view[4], V11 = view[5], V12 = view[6];
    const float V20 = view[8], V21 = view[9], V22 = view[10];
    const float T00 = J00 * V00 + J02 * V20;
    const float T01 = J00 * V01 + J02 * V21;
    const float T02 = J00 * V02 + J02 * V22;
    const float T10 = J11 * V10 + J12 * V20;
    const float T11 = J11 * V11 + J12 * V21;
    const float T12 = J11 * V12 + J12 * V22;

    // cov2d = Tm C Tm^T (2x2)
    const float u0 = C00 * T00 + C01 * T01 + C02 * T02;
    const float u1 = C01 * T00 + C11 * T01 + C12 * T02;
    const float u2 = C02 * T00 + C12 * T01 + C22 * T02;
    const float w0 = C00 * T10 + C01 * T11 + C02 * T12;
    const float w1 = C01 * T10 + C11 * T11 + C12 * T12;
    const float w2 = C02 * T10 + C12 * T11 + C22 * T12;
    const float a = T00 * u0 + T01 * u1 + T02 * u2 + 0.3f;
    const float b = T10 * u0 + T11 * u1 + T12 * u2;
    const float c = T10 * w0 + T11 * w1 + T12 * w2 + 0.3f;

    const float det = a * c - b * b;
    const float inv_det = 1.0f / ((det != 0.0f) ? det : 1.0f);
    float ca =  c * inv_det;
    float cb = -b * inv_det;
    float cc =  a * inv_det;

    const float mid = 0.5f * (a + c);
    const float lam = mid + sqrtf(fmaxf(mid * mid - det, 0.1f));
    radii_out[i] = (float)((int)ceilf(3.0f * sqrtf(lam)));

    const bool valid = (depth > 0.2f) && (det > 0.0f);
    float op = opac[i];
    if (!valid) { ca = 0.0f; cb = 0.0f; cc = 0.0f; op = 0.0f; }

    __syncthreads();
    // stable rank of depth (ascending)
    const float d = sdepth[i];
    int rank = 0;
    #pragma unroll 8
    for (int j = 0; j < NG; ++j) {
        const float dj = sdepth[j];
        rank += (dj < d) || ((dj == d) && (j < i));
    }

    GData g;
    g.A = make_float4(px, py, ca, cb);
    g.B = make_float4(cc, op, colors[3 * i + 0], colors[3 * i + 1]);
    g.C = make_float4(colors[3 * i + 2], 1.0f / fmaxf(depth, 1e-6f), 0.0f, 0.0f);
    g_sorted[rank] = g;
}

// ---------------------------------------------------------------------------
// Raster: 16x16 pixel tiles, all 512 sorted gaussians staged in smem
// ---------------------------------------------------------------------------
__global__ void __launch_bounds__(256)
raster_kernel(const float* __restrict__ bg,
              const float* __restrict__ mask,
              float* __restrict__ out)
{
    __shared__ float4 sg[NG * 3];
    const int tid = threadIdx.y * 16 + threadIdx.x;
    const float4* src = reinterpret_cast<const float4*>(g_sorted);
    #pragma unroll
    for (int i = tid; i < NG * 3; i += 256) sg[i] = src[i];
    __syncthreads();

    const int x = blockIdx.x * 16 + threadIdx.x;
    const int y = blockIdx.y * 16 + threadIdx.y;
    const float fx = (float)x;
    const float fy = (float)y;

    float T = 1.0f, aR = 0.0f, aG = 0.0f, aB = 0.0f, aD = 0.0f;

    for (int n = 0; n < NG; ++n) {
        const float4 A = sg[3 * n + 0];
        const float dx = fx - A.x;
        const float dy = fy - A.y;
        const float power = -0.5f * (A.z * dx * dx) - A.w * dx * dy
                            - 0.5f * (sg[3 * n + 1].x * dy * dy);
        if (power > 0.0f) continue;
        const float4 B = sg[3 * n + 1];
        const float alpha = fminf(0.99f, B.y * expf(power));
        if (alpha < (1.0f / 255.0f)) continue;
        const float4 C = sg[3 * n + 2];
        const float w = alpha * T;
        aR += w * B.z;
        aG += w * B.w;
        aB += w * C.x;
        aD += w * C.y;
        T *= (1.0f - alpha);
        if (T < 1e-7f) break;
    }

    const int pix = y * IMG_W + x;
    const float m = mask[pix];
    const int HW = IMG_H * IMG_W;
    out[0 * HW + pix] = (aR + T * bg[0]) * m;
    out[1 * HW + pix] = (aG + T * bg[1]) * m;
    out[2 * HW + pix] = (aB + T * bg[2]) * m;
    out[3 * HW + NG + pix] = aD * m;   // invd after color(3*HW) + radii(NG)
}

// ---------------------------------------------------------------------------
extern "C" void kernel_launch(void* const* d_in, const int* in_sizes, int n_in,
                              void* d_out, int out_size)
{
    const float* means3D = (const float*)d_in[0];
    // d_in[1] = means2D (unused by reference math)
    const float* opac    = (const float*)d_in[2];
    const float* colors  = (const float*)d_in[3];
    const float* scales  = (const float*)d_in[4];
    const float* rots    = (const float*)d_in[5];
    const float* view    = (const float*)d_in[6];
    const float* proj    = (const float*)d_in[7];
    const float* bg      = (const float*)d_in[8];
    const float* mask    = (const float*)d_in[9];
    float* out = (float*)d_out;

    float* radii_out = out + 3 * IMG_H * IMG_W;

    preprocess_kernel<<<1, NG>>>(means3D, opac, colors, scales, rots,
                                 view, proj, radii_out);

    dim3 blk(16, 16);
    dim3 grd(IMG_W / 16, IMG_H / 16);
    raster_kernel<<<grd, blk>>>(bg, mask, out);
}

// round 2
// speedup vs baseline: 3.2904x; 3.2904x over previous
#include <cuda_runtime.h>
#include <math.h>
#include <stdint.h>

#define NG 512
#define IMG_H 256
#define IMG_W 256

#define FXC 256.0f
#define FYC 256.0f
#define LIMX (1.3f * 0.5f)
#define LIMY (1.3f * 0.5f)

// Sorted per-gaussian data, 48 bytes (3 x float4) each:
//  A: px, py, ca, cb    B: cc, op, cr, cg    C: cb(blue), invdepth, pad, pad
struct __align__(16) GData { float4 A, B, C; };
__device__ GData g_sorted[NG];
// Sorted cull info: px, py, r2 (cull radius squared; <0 => never visible), pad
__device__ float4 g_cull[NG];

// ---------------------------------------------------------------------------
// Preprocess: 1 block, 512 threads (one gaussian each) + in-block stable sort
// ---------------------------------------------------------------------------
__global__ void __launch_bounds__(NG)
preprocess_kernel(const float* __restrict__ means3D,
                  const float* __restrict__ opac,
                  const float* __restrict__ colors,
                  const float* __restrict__ scales,
                  const float* __restrict__ rots,
                  const float* __restrict__ view,
                  const float* __restrict__ proj,
                  float* __restrict__ radii_out)
{
    const int i = threadIdx.x;
    __shared__ float sdepth[NG];

    const float m0 = means3D[3 * i + 0];
    const float m1 = means3D[3 * i + 1];
    const float m2 = means3D[3 * i + 2];

    // t = view @ [m,1]
    const float t0 = view[0] * m0 + view[1] * m1 + view[2]  * m2 + view[3];
    const float t1 = view[4] * m0 + view[5] * m1 + view[6]  * m2 + view[7];
    const float t2 = view[8] * m0 + view[9] * m1 + view[10] * m2 + view[11];
    const float depth = t2;
    sdepth[i] = depth;

    // clip = proj @ [m,1]
    const float c0 = proj[0]  * m0 + proj[1]  * m1 + proj[2]  * m2 + proj[3];
    const float c1 = proj[4]  * m0 + proj[5]  * m1 + proj[6]  * m2 + proj[7];
    const float c3 = proj[12] * m0 + proj[13] * m1 + proj[14] * m2 + proj[15];
    const float pw = 1.0f / (c3 + 1e-7f);
    const float px = ((c0 * pw + 1.0f) * (float)IMG_W - 1.0f) * 0.5f;
    const float py = ((c1 * pw + 1.0f) * (float)IMG_H - 1.0f) * 0.5f;

    // quaternion -> rotation
    float qw = rots[4 * i + 0], qx = rots[4 * i + 1],
          qy = rots[4 * i + 2], qz = rots[4 * i + 3];
    const float qn = rsqrtf(qw * qw + qx * qx + qy * qy + qz * qz);
    qw *= qn; qx *= qn; qy *= qn; qz *= qn;
    const float R00 = 1.0f - 2.0f * (qy * qy + qz * qz);
    const float R01 = 2.0f * (qx * qy - qw * qz);
    const float R02 = 2.0f * (qx * qz + qw * qy);
    const float R10 = 2.0f * (qx * qy + qw * qz);
    const float R11 = 1.0f - 2.0f * (qx * qx + qz * qz);
    const float R12 = 2.0f * (qy * qz - qw * qx);
    const float R20 = 2.0f * (qx * qz - qw * qy);
    const float R21 = 2.0f * (qy * qz + qw * qx);
    const float R22 = 1.0f - 2.0f * (qx * qx + qy * qy);

    const float s0 = scales[3 * i + 0];
    const float s1 = scales[3 * i + 1];
    const float s2 = scales[3 * i + 2];

    // M = R * diag(s); cov3d = M M^T
    const float M00 = R00 * s0, M01 = R01 * s1, M02 = R02 * s2;
    const float M10 = R10 * s0, M11 = R11 * s1, M12 = R12 * s2;
    const float M20 = R20 * s0, M21 = R21 * s1, M22 = R22 * s2;
    const float C00 = M00 * M00 + M01 * M01 + M02 * M02;
    const float C01 = M00 * M10 + M01 * M11 + M02 * M12;
    const float C02 = M00 * M20 + M01 * M21 + M02 * M22;
    const float C11 = M10 * M10 + M11 * M11 + M12 * M12;
    const float C12 = M10 * M20 + M11 * M21 + M12 * M22;
    const float C22 = M20 * M20 + M21 * M21 + M22 * M22;

    // EWA Jacobian
    const float tz   = depth;
    const float invz = 1.0f / tz;
    const float tx = fminf(fmaxf(t0 * invz, -LIMX), LIMX) * tz;
    const float ty = fminf(fmaxf(t1 * invz, -LIMY), LIMY) * tz;
    const float J00 = FXC * invz;
    const float J02 = -FXC * tx * invz * invz;
    const float J11 = FYC * invz;
    const float J12 = -FYC * ty * invz * invz;

    // Tm = J(2x3) @ V3(3x3)
    const float V00 = view[0], V01 = view[1], V02 = view[2];
    const float V10 = view[4], V11 = view[5], V12 = view[6];
    const float V20 = view[8], V21 = view[9], V22 = view[10];
    const float T00 = J00 * V00 + J02 * V20;
    const float T01 = J00 * V01 + J02 * V21;
    const float T02 = J00 * V02 + J02 * V22;
    const float T10 = J11 * V10 + J12 * V20;
    const float T11 = J11 * V11 + J12 * V21;
    const float T12 = J11 * V12 + J12 * V22;

    // cov2d = Tm C Tm^T (2x2)
    const float u0 = C00 * T00 + C01 * T01 + C02 * T02;
    const float u1 = C01 * T00 + C11 * T01 + C12 * T02;
    const float u2 = C02 * T00 + C12 * T01 + C22 * T02;
    const float w0 = C00 * T10 + C01 * T11 + C02 * T12;
    const float w1 = C01 * T10 + C11 * T11 + C12 * T12;
    const float w2 = C02 * T10 + C12 * T11 + C22 * T12;
    const float a = T00 * u0 + T01 * u1 + T02 * u2 + 0.3f;
    const float b = T10 * u0 + T11 * u1 + T12 * u2;
    const float c = T10 * w0 + T11 * w1 + T12 * w2 + 0.3f;

    const float det = a * c - b * b;
    const float inv_det = 1.0f / ((det != 0.0f) ? det : 1.0f);
    float ca =  c * inv_det;
    float cb = -b * inv_det;
    float cc =  a * inv_det;

    const float mid = 0.5f * (a + c);
    const float lam = mid + sqrtf(fmaxf(mid * mid - det, 0.1f));
    radii_out[i] = (float)((int)ceilf(3.0f * sqrtf(lam)));

    const bool valid = (depth > 0.2f) && (det > 0.0f);
    float op = opac[i];
    if (!valid) { ca = 0.0f; cb = 0.0f; cc = 0.0f; op = 0.0f; }

    // Exact cull radius: alpha = op*exp(power) with power <= -|d|^2/(2*lam)
    // => alpha < 1/255 guaranteed when |d|^2 > 2*lam*ln(255*op).
    float r2 = -1.0f;
    if (valid && op * 255.0f > 1.0f) {
        r2 = 2.0f * lam * logf(255.0f * op) + 1e-2f;  // small safety margin
        if (r2 < 0.0f) r2 = -1.0f;
    }

    __syncthreads();
    // stable rank of depth (ascending)
    const float d = sdepth[i];
    int rank = 0;
    #pragma unroll 8
    for (int j = 0; j < NG; ++j) {
        const float dj = sdepth[j];
        rank += (dj < d) || ((dj == d) && (j < i));
    }

    GData g;
    g.A = make_float4(px, py, ca, cb);
    g.B = make_float4(cc, op, colors[3 * i + 0], colors[3 * i + 1]);
    g.C = make_float4(colors[3 * i + 2], 1.0f / fmaxf(depth, 1e-6f), 0.0f, 0.0f);
    g_sorted[rank] = g;
    g_cull[rank] = make_float4(px, py, r2, 0.0f);
}

// ---------------------------------------------------------------------------
// Raster: 16x16 pixel tiles. Phase 1: exact tile-cull -> 512-bit bitmask.
// Phase 2: order-preserving compaction into smem. Phase 3: composite.
// ---------------------------------------------------------------------------
__global__ void __launch_bounds__(256)
raster_kernel(const float* __restrict__ bg,
              const float* __restrict__ mask,
              float* __restrict__ out)
{
    __shared__ uint32_t bm[16];
    __shared__ int s_count;
    __shared__ float4 sg[NG * 3];

    const int tid = threadIdx.y * 16 + threadIdx.x;
    if (tid < 16) bm[tid] = 0u;
    __syncthreads();

    const float tx0 = (float)(blockIdx.x * 16);
    const float tx1 = tx0 + 15.0f;
    const float ty0 = (float)(blockIdx.y * 16);
    const float ty1 = ty0 + 15.0f;

    // Phase 1: intersection test (2 gaussians per thread)
    #pragma unroll
    for (int j = tid; j < NG; j += 256) {
        const float4 cg = g_cull[j];
        const float cx = fminf(fmaxf(cg.x, tx0), tx1);
        const float cy = fminf(fmaxf(cg.y, ty0), ty1);
        const float ddx = cg.x - cx;
        const float ddy = cg.y - cy;
        if (ddx * ddx + ddy * ddy <= cg.z)
            atomicOr(&bm[j >> 5], 1u << (j & 31));
    }
    __syncthreads();

    // Phase 2: compaction preserving depth order
    #pragma unroll
    for (int j = tid; j < NG; j += 256) {
        const uint32_t w = bm[j >> 5];
        const uint32_t bit = 1u << (j & 31);
        if (w & bit) {
            int pos = __popc(w & (bit - 1u));
            for (int k = 0; k < (j >> 5); ++k) pos += __popc(bm[k]);
            const float4* src = reinterpret_cast<const float4*>(&g_sorted[j]);
            sg[3 * pos + 0] = src[0];
            sg[3 * pos + 1] = src[1];
            sg[3 * pos + 2] = src[2];
        }
    }
    if (tid == 0) {
        int cnt = 0;
        #pragma unroll
        for (int k = 0; k < 16; ++k) cnt += __popc(bm[k]);
        s_count = cnt;
    }
    __syncthreads();
    const int count = s_count;

    // Phase 3: front-to-back composite
    const int x = blockIdx.x * 16 + threadIdx.x;
    const int y = blockIdx.y * 16 + threadIdx.y;
    const float fx = (float)x;
    const float fy = (float)y;

    float T = 1.0f, aR = 0.0f, aG = 0.0f, aB = 0.0f, aD = 0.0f;

    for (int n = 0; n < count; ++n) {
        const float4 A = sg[3 * n + 0];
        const float dx = fx - A.x;
        const float dy = fy - A.y;
        const float power = -0.5f * (A.z * dx * dx) - A.w * dx * dy
                            - 0.5f * (sg[3 * n + 1].x * dy * dy);
        if (power > 0.0f) continue;
        const float4 B = sg[3 * n + 1];
        const float alpha = fminf(0.99f, B.y * __expf(power));
        if (alpha < (1.0f / 255.0f)) continue;
        const float4 C = sg[3 * n + 2];
        const float w = alpha * T;
        aR += w * B.z;
        aG += w * B.w;
        aB += w * C.x;
        aD += w * C.y;
        T *= (1.0f - alpha);
        if (T < 1e-7f) break;
    }

    const int pix = y * IMG_W + x;
    const float m = mask[pix];
    const int HW = IMG_H * IMG_W;
    out[0 * HW + pix] = (aR + T * bg[0]) * m;
    out[1 * HW + pix] = (aG + T * bg[1]) * m;
    out[2 * HW + pix] = (aB + T * bg[2]) * m;
    out[3 * HW + NG + pix] = aD * m;   // invd after color(3*HW) + radii(NG)
}

// ---------------------------------------------------------------------------
extern "C" void kernel_launch(void* const* d_in, const int* in_sizes, int n_in,
                              void* d_out, int out_size)
{
    const float* means3D = (const float*)d_in[0];
    // d_in[1] = means2D (unused by reference math)
    const float* opac    = (const float*)d_in[2];
    const float* colors  = (const float*)d_in[3];
    const float* scales  = (const float*)d_in[4];
    const float* rots    = (const float*)d_in[5];
    const float* view    = (const float*)d_in[6];
    const float* proj    = (const float*)d_in[7];
    const float* bg      = (const float*)d_in[8];
    const float* mask    = (const float*)d_in[9];
    float* out = (float*)d_out;

    float* radii_out = out + 3 * IMG_H * IMG_W;

    preprocess_kernel<<<1, NG>>>(means3D, opac, colors, scales, rots,
                                 view, proj, radii_out);

    dim3 blk(16, 16);
    dim3 grd(IMG_W / 16, IMG_H / 16);
    raster_kernel<<<grd, blk>>>(bg, mask, out);
}

// round 3
// speedup vs baseline: 5.1394x; 1.5619x over previous
#include <cuda_runtime.h>
#include <math.h>
#include <stdint.h>

#define NG 512
#define IMG_H 256
#define IMG_W 256

#define FXC 256.0f
#define FYC 256.0f
#define LIMX (1.3f * 0.5f)
#define LIMY (1.3f * 0.5f)

// Sorted per-gaussian data, 48 bytes (3 x float4) each:
//  A: px, py, ca, cb    B: cc, op, cr, cg    C: cb(blue), invdepth, pad, pad
struct __align__(16) GData { float4 A, B, C; };
__device__ GData g_sorted[NG];
// Sorted cull info: px, py, r2 (cull radius squared; <0 => never visible), pad
__device__ float4 g_cull[NG];

// ---------------------------------------------------------------------------
// Preprocess: 16 blocks x 32 threads, one gaussian per thread.
// Each block recomputes all 512 depths into smem (cheap: 3 FMA each),
// then ranks + scatters its own 32 gaussians.
// ---------------------------------------------------------------------------
__global__ void __launch_bounds__(32)
preprocess_kernel(const float* __restrict__ means3D,
                  const float* __restrict__ opac,
                  const float* __restrict__ colors,
                  const float* __restrict__ scales,
                  const float* __restrict__ rots,
                  const float* __restrict__ view,
                  const float* __restrict__ proj,
                  float* __restrict__ radii_out)
{
    const int i = blockIdx.x * 32 + threadIdx.x;   // gaussian id
    __shared__ __align__(16) float sdepth[NG];

    const float v8 = view[8], v9 = view[9], v10 = view[10], v11 = view[11];

    // All 512 depths, cooperatively (16 per thread)
    #pragma unroll
    for (int j = threadIdx.x; j < NG; j += 32) {
        const float a0 = means3D[3 * j + 0];
        const float a1 = means3D[3 * j + 1];
        const float a2 = means3D[3 * j + 2];
        sdepth[j] = v8 * a0 + v9 * a1 + v10 * a2 + v11;
    }
    __syncthreads();

    const float m0 = means3D[3 * i + 0];
    const float m1 = means3D[3 * i + 1];
    const float m2 = means3D[3 * i + 2];

    // t = view @ [m,1]
    const float t0 = view[0] * m0 + view[1] * m1 + view[2]  * m2 + view[3];
    const float t1 = view[4] * m0 + view[5] * m1 + view[6]  * m2 + view[7];
    const float depth = sdepth[i];

    // clip = proj @ [m,1]
    const float c0 = proj[0]  * m0 + proj[1]  * m1 + proj[2]  * m2 + proj[3];
    const float c1 = proj[4]  * m0 + proj[5]  * m1 + proj[6]  * m2 + proj[7];
    const float c3 = proj[12] * m0 + proj[13] * m1 + proj[14] * m2 + proj[15];
    const float pw = 1.0f / (c3 + 1e-7f);
    const float px = ((c0 * pw + 1.0f) * (float)IMG_W - 1.0f) * 0.5f;
    const float py = ((c1 * pw + 1.0f) * (float)IMG_H - 1.0f) * 0.5f;

    // quaternion -> rotation
    float qw = rots[4 * i + 0], qx = rots[4 * i + 1],
          qy = rots[4 * i + 2], qz = rots[4 * i + 3];
    const float qn = rsqrtf(qw * qw + qx * qx + qy * qy + qz * qz);
    qw *= qn; qx *= qn; qy *= qn; qz *= qn;
    const float R00 = 1.0f - 2.0f * (qy * qy + qz * qz);
    const float R01 = 2.0f * (qx * qy - qw * qz);
    const float R02 = 2.0f * (qx * qz + qw * qy);
    const float R10 = 2.0f * (qx * qy + qw * qz);
    const float R11 = 1.0f - 2.0f * (qx * qx + qz * qz);
    const float R12 = 2.0f * (qy * qz - qw * qx);
    const float R20 = 2.0f * (qx * qz - qw * qy);
    const float R21 = 2.0f * (qy * qz + qw * qx);
    const float R22 = 1.0f - 2.0f * (qx * qx + qy * qy);

    const float s0 = scales[3 * i + 0];
    const float s1 = scales[3 * i + 1];
    const float s2 = scales[3 * i + 2];

    // M = R * diag(s); cov3d = M M^T
    const float M00 = R00 * s0, M01 = R01 * s1, M02 = R02 * s2;
    const float M10 = R10 * s0, M11 = R11 * s1, M12 = R12 * s2;
    const float M20 = R20 * s0, M21 = R21 * s1, M22 = R22 * s2;
    const float C00 = M00 * M00 + M01 * M01 + M02 * M02;
    const float C01 = M00 * M10 + M01 * M11 + M02 * M12;
    const float C02 = M00 * M20 + M01 * M21 + M02 * M22;
    const float C11 = M10 * M10 + M11 * M11 + M12 * M12;
    const float C12 = M10 * M20 + M11 * M21 + M12 * M22;
    const float C22 = M20 * M20 + M21 * M21 + M22 * M22;

    // EWA Jacobian
    const float tz   = depth;
    const float invz = 1.0f / tz;
    const float tx = fminf(fmaxf(t0 * invz, -LIMX), LIMX) * tz;
    const float ty = fminf(fmaxf(t1 * invz, -LIMY), LIMY) * tz;
    const float J00 = FXC * invz;
    const float J02 = -FXC * tx * invz * invz;
    const float J11 = FYC * invz;
    const float J12 = -FYC * ty * invz * invz;

    // Tm = J(2x3) @ V3(3x3)
    const float V00 = view[0], V01 = view[1], V02 = view[2];
    const float V10 = view[4], V11 = view[5], V12 = view[6];
    const float V20 = v8,      V21 = v9,      V22 = v10;
    const float T00 = J00 * V00 + J02 * V20;
    const float T01 = J00 * V01 + J02 * V21;
    const float T02 = J00 * V02 + J02 * V22;
    const float T10 = J11 * V10 + J12 * V20;
    const float T11 = J11 * V11 + J12 * V21;
    const float T12 = J11 * V12 + J12 * V22;

    // cov2d = Tm C Tm^T (2x2)
    const float u0 = C00 * T00 + C01 * T01 + C02 * T02;
    const float u1 = C01 * T00 + C11 * T01 + C12 * T02;
    const float u2 = C02 * T00 + C12 * T01 + C22 * T02;
    const float w0 = C00 * T10 + C01 * T11 + C02 * T12;
    const float w1 = C01 * T10 + C11 * T11 + C12 * T12;
    const float w2 = C02 * T10 + C12 * T11 + C22 * T12;
    const float a = T00 * u0 + T01 * u1 + T02 * u2 + 0.3f;
    const float b = T10 * u0 + T11 * u1 + T12 * u2;
    const float c = T10 * w0 + T11 * w1 + T12 * w2 + 0.3f;

    const float det = a * c - b * b;
    const float inv_det = 1.0f / ((det != 0.0f) ? det : 1.0f);
    float ca =  c * inv_det;
    float cb = -b * inv_det;
    float cc =  a * inv_det;

    const float mid = 0.5f * (a + c);
    const float lam = mid + sqrtf(fmaxf(mid * mid - det, 0.1f));
    radii_out[i] = (float)((int)ceilf(3.0f * sqrtf(lam)));

    const bool valid = (depth > 0.2f) && (det > 0.0f);
    float op = opac[i];
    if (!valid) { ca = 0.0f; cb = 0.0f; cc = 0.0f; op = 0.0f; }

    // Exact cull radius: alpha = op*exp(power) with power <= -|d|^2/(2*lam)
    // => alpha < 1/255 guaranteed when |d|^2 > 2*lam*ln(255*op).
    float r2 = -1.0f;
    if (valid && op * 255.0f > 1.0f) {
        r2 = 2.0f * lam * logf(255.0f * op) + 1e-2f;  // small safety margin
        if (r2 < 0.0f) r2 = -1.0f;
    }

    // stable rank of depth (ascending), vectorized smem reads
    const float d = depth;
    int rank = 0;
    const float4* sd4 = reinterpret_cast<const float4*>(sdepth);
    #pragma unroll 4
    for (int k = 0; k < NG / 4; ++k) {
        const float4 dj = sd4[k];
        const int j = 4 * k;
        rank += (dj.x < d) || ((dj.x == d) && (j + 0 < i));
        rank += (dj.y < d) || ((dj.y == d) && (j + 1 < i));
        rank += (dj.z < d) || ((dj.z == d) && (j + 2 < i));
        rank += (dj.w < d) || ((dj.w == d) && (j + 3 < i));
    }

    GData g;
    g.A = make_float4(px, py, ca, cb);
    g.B = make_float4(cc, op, colors[3 * i + 0], colors[3 * i + 1]);
    g.C = make_float4(colors[3 * i + 2], 1.0f / fmaxf(depth, 1e-6f), 0.0f, 0.0f);
    g_sorted[rank] = g;
    g_cull[rank] = make_float4(px, py, r2, 0.0f);
}

// ---------------------------------------------------------------------------
// Raster: 16x16 pixel tiles. Phase 1: exact tile-cull via warp ballot.
// Phase 2: order-preserving compaction (word-prefix table). Phase 3: composite.
// ---------------------------------------------------------------------------
__global__ void __launch_bounds__(256)
raster_kernel(const float* __restrict__ bg,
              const float* __restrict__ mask,
              float* __restrict__ out)
{
    __shared__ uint32_t bm[16];
    __shared__ int wpre[17];          // word prefix sums
    __shared__ float4 sg[NG * 3];

    const int tid  = threadIdx.y * 16 + threadIdx.x;
    const int warp = tid >> 5;
    const int lane = tid & 31;

    const float tx0 = (float)(blockIdx.x * 16);
    const float tx1 = tx0 + 15.0f;
    const float ty0 = (float)(blockIdx.y * 16);
    const float ty1 = ty0 + 15.0f;

    // Phase 1: intersection test. Warp w's ballot for j=w*32+lane IS word w.
    #pragma unroll
    for (int half = 0; half < 2; ++half) {
        const int j = half * 256 + tid;
        const float4 cg = g_cull[j];
        const float cx = fminf(fmaxf(cg.x, tx0), tx1);
        const float cy = fminf(fmaxf(cg.y, ty0), ty1);
        const float ddx = cg.x - cx;
        const float ddy = cg.y - cy;
        const uint32_t bal = __ballot_sync(0xFFFFFFFFu,
                                           ddx * ddx + ddy * ddy <= cg.z);
        if (lane == 0) bm[half * 8 + warp] = bal;
    }
    __syncthreads();

    // Word prefix sums (single thread; 16 words)
    if (tid == 0) {
        int acc = 0;
        #pragma unroll
        for (int k = 0; k < 16; ++k) { wpre[k] = acc; acc += __popc(bm[k]); }
        wpre[16] = acc;
    }
    __syncthreads();

    // Phase 2: compaction preserving depth order
    #pragma unroll
    for (int half = 0; half < 2; ++half) {
        const int j = half * 256 + tid;
        const uint32_t w = bm[j >> 5];
        const uint32_t bit = 1u << (j & 31);
        if (w & bit) {
            const int pos = wpre[j >> 5] + __popc(w & (bit - 1u));
            const float4* src = reinterpret_cast<const float4*>(&g_sorted[j]);
            sg[3 * pos + 0] = src[0];
            sg[3 * pos + 1] = src[1];
            sg[3 * pos + 2] = src[2];
        }
    }
    __syncthreads();
    const int count = wpre[16];

    // Phase 3: front-to-back composite
    const int x = blockIdx.x * 16 + threadIdx.x;
    const int y = blockIdx.y * 16 + threadIdx.y;
    const float fx = (float)x;
    const float fy = (float)y;

    float T = 1.0f, aR = 0.0f, aG = 0.0f, aB = 0.0f, aD = 0.0f;

    for (int n = 0; n < count; ++n) {
        const float4 A = sg[3 * n + 0];
        const float dx = fx - A.x;
        const float dy = fy - A.y;
        const float power = -0.5f * (A.z * dx * dx) - A.w * dx * dy
                            - 0.5f * (sg[3 * n + 1].x * dy * dy);
        if (power > 0.0f) continue;
        const float4 B = sg[3 * n + 1];
        const float alpha = fminf(0.99f, B.y * __expf(power));
        if (alpha < (1.0f / 255.0f)) continue;
        const float4 C = sg[3 * n + 2];
        const float w = alpha * T;
        aR += w * B.z;
        aG += w * B.w;
        aB += w * C.x;
        aD += w * C.y;
        T *= (1.0f - alpha);
        if (T < 1e-7f) break;
    }

    const int pix = y * IMG_W + x;
    const float m = mask[pix];
    const int HW = IMG_H * IMG_W;
    out[0 * HW + pix] = (aR + T * bg[0]) * m;
    out[1 * HW + pix] = (aG + T * bg[1]) * m;
    out[2 * HW + pix] = (aB + T * bg[2]) * m;
    out[3 * HW + NG + pix] = aD * m;   // invd after color(3*HW) + radii(NG)
}

// ---------------------------------------------------------------------------
extern "C" void kernel_launch(void* const* d_in, const int* in_sizes, int n_in,
                              void* d_out, int out_size)
{
    const float* means3D = (const float*)d_in[0];
    // d_in[1] = means2D (unused by reference math)
    const float* opac    = (const float*)d_in[2];
    const float* colors  = (const float*)d_in[3];
    const float* scales  = (const float*)d_in[4];
    const float* rots    = (const float*)d_in[5];
    const float* view    = (const float*)d_in[6];
    const float* proj    = (const float*)d_in[7];
    const float* bg      = (const float*)d_in[8];
    const float* mask    = (const float*)d_in[9];
    float* out = (float*)d_out;

    float* radii_out = out + 3 * IMG_H * IMG_W;

    preprocess_kernel<<<16, 32>>>(means3D, opac, colors, scales, rots,
                                  view, proj, radii_out);

    dim3 blk(16, 16);
    dim3 grd(IMG_W / 16, IMG_H / 16);
    raster_kernel<<<grd, blk>>>(bg, mask, out);
}

// round 6
// speedup vs baseline: 5.8221x; 1.1328x over previous
#include <cuda_runtime.h>
#include <math.h>
#include <stdint.h>

#define NG 512
#define IMG_H 256
#define IMG_W 256
#define TW 16
#define TH 8
#define NTHR 128

#define FXC 256.0f
#define FYC 256.0f
#define LIMX (1.3f * 0.5f)
#define LIMY (1.3f * 0.5f)

// ---------------------------------------------------------------------------
// Fully fused: each block = one 16x8 pixel tile. The block preprocesses all
// 512 gaussians itself (4/thread), culls against its tile with the exact
// alpha>=1/255 bound, sorts the ~10-30 survivors by (depth, index) — which
// reproduces the reference's stable depth argsort among contributing
// gaussians — then composites front-to-back.
// Static smem: 3*512*16 + 512*4*3 + 4 = 30724 B (< 48 KB static cap).
// ---------------------------------------------------------------------------
__global__ void __launch_bounds__(NTHR)
fused_kernel(const float* __restrict__ means3D,
             const float* __restrict__ opac,
             const float* __restrict__ colors,
             const float* __restrict__ scales,
             const float* __restrict__ rots,
             const float* __restrict__ view,
             const float* __restrict__ proj,
             const float* __restrict__ bg,
             const float* __restrict__ mask,
             float* __restrict__ out)
{
    __shared__ float4 sgA[NG];     // survivors: px, py, ca, cb
    __shared__ float4 sgB[NG];     // cc, op, cr, cg
    __shared__ float4 sgC[NG];     // cb(blue), invdepth, -, -
    __shared__ float  sdep[NG];
    __shared__ int    sidx[NG];
    __shared__ int    ord[NG];     // ord[rank] = slot
    __shared__ int    s_cnt;

    const int tid = threadIdx.y * TW + threadIdx.x;
    if (tid == 0) s_cnt = 0;
    __syncthreads();

    const float tx0 = (float)(blockIdx.x * TW);
    const float tx1 = tx0 + (float)(TW - 1);
    const float ty0 = (float)(blockIdx.y * TH);
    const float ty1 = ty0 + (float)(TH - 1);
    const bool block0 = (blockIdx.x == 0) && (blockIdx.y == 0);

    // Broadcast camera constants
    const float V00 = view[0], V01 = view[1], V02 = view[2],  V03 = view[3];
    const float V10 = view[4], V11 = view[5], V12 = view[6],  V13 = view[7];
    const float V20 = view[8], V21 = view[9], V22 = view[10], V23 = view[11];
    const float P00 = proj[0],  P01 = proj[1],  P02 = proj[2],  P03 = proj[3];
    const float P10 = proj[4],  P11 = proj[5],  P12 = proj[6],  P13 = proj[7];
    const float P30 = proj[12], P31 = proj[13], P32 = proj[14], P33 = proj[15];

    // ---- Per-gaussian preprocess + cull (4 gaussians per thread) ----
    #pragma unroll 1
    for (int k = 0; k < NG / NTHR; ++k) {
        const int j = tid + NTHR * k;

        const float m0 = means3D[3 * j + 0];
        const float m1 = means3D[3 * j + 1];
        const float m2 = means3D[3 * j + 2];

        const float t0 = V00 * m0 + V01 * m1 + V02 * m2 + V03;
        const float t1 = V10 * m0 + V11 * m1 + V12 * m2 + V13;
        const float depth = V20 * m0 + V21 * m1 + V22 * m2 + V23;

        const float c0 = P00 * m0 + P01 * m1 + P02 * m2 + P03;
        const float c1 = P10 * m0 + P11 * m1 + P12 * m2 + P13;
        const float c3 = P30 * m0 + P31 * m1 + P32 * m2 + P33;
        const float pw = 1.0f / (c3 + 1e-7f);
        const float px = ((c0 * pw + 1.0f) * (float)IMG_W - 1.0f) * 0.5f;
        const float py = ((c1 * pw + 1.0f) * (float)IMG_H - 1.0f) * 0.5f;

        float qw = rots[4 * j + 0], qx = rots[4 * j + 1],
              qy = rots[4 * j + 2], qz = rots[4 * j + 3];
        const float qn = rsqrtf(qw * qw + qx * qx + qy * qy + qz * qz);
        qw *= qn; qx *= qn; qy *= qn; qz *= qn;
        const float R00 = 1.0f - 2.0f * (qy * qy + qz * qz);
        const float R01 = 2.0f * (qx * qy - qw * qz);
        const float R02 = 2.0f * (qx * qz + qw * qy);
        const float R10 = 2.0f * (qx * qy + qw * qz);
        const float R11 = 1.0f - 2.0f * (qx * qx + qz * qz);
        const float R12 = 2.0f * (qy * qz - qw * qx);
        const float R20 = 2.0f * (qx * qz - qw * qy);
        const float R21 = 2.0f * (qy * qz + qw * qx);
        const float R22 = 1.0f - 2.0f * (qx * qx + qy * qy);

        const float s0 = scales[3 * j + 0];
        const float s1 = scales[3 * j + 1];
        const float s2 = scales[3 * j + 2];

        const float M00 = R00 * s0, M01 = R01 * s1, M02 = R02 * s2;
        const float M10 = R10 * s0, M11 = R11 * s1, M12 = R12 * s2;
        const float M20 = R20 * s0, M21 = R21 * s1, M22 = R22 * s2;
        const float C00 = M00 * M00 + M01 * M01 + M02 * M02;
        const float C01 = M00 * M10 + M01 * M11 + M02 * M12;
        const float C02 = M00 * M20 + M01 * M21 + M02 * M22;
        const float C11 = M10 * M10 + M11 * M11 + M12 * M12;
        const float C12 = M10 * M20 + M11 * M21 + M12 * M22;
        const float C22 = M20 * M20 + M21 * M21 + M22 * M22;

        const float invz = 1.0f / depth;
        const float ttx = fminf(fmaxf(t0 * invz, -LIMX), LIMX) * depth;
        const float tty = fminf(fmaxf(t1 * invz, -LIMY), LIMY) * depth;
        const float J00 = FXC * invz;
        const float J02 = -FXC * ttx * invz * invz;
        const float J11 = FYC * invz;
        const float J12 = -FYC * tty * invz * invz;

        const float T00 = J00 * V00 + J02 * V20;
        const float T01 = J00 * V01 + J02 * V21;
        const float T02 = J00 * V02 + J02 * V22;
        const float T10 = J11 * V10 + J12 * V20;
        const float T11 = J11 * V11 + J12 * V21;
        const float T12 = J11 * V12 + J12 * V22;

        const float u0 = C00 * T00 + C01 * T01 + C02 * T02;
        const float u1 = C01 * T00 + C11 * T01 + C12 * T02;
        const float u2 = C02 * T00 + C12 * T01 + C22 * T02;
        const float w0 = C00 * T10 + C01 * T11 + C02 * T12;
        const float w1 = C01 * T10 + C11 * T11 + C12 * T12;
        const float w2 = C02 * T10 + C12 * T11 + C22 * T12;
        const float a = T00 * u0 + T01 * u1 + T02 * u2 + 0.3f;
        const float b = T10 * u0 + T11 * u1 + T12 * u2;
        const float c = T10 * w0 + T11 * w1 + T12 * w2 + 0.3f;

        const float det = a * c - b * b;
        const float inv_det = 1.0f / ((det != 0.0f) ? det : 1.0f);
        const float ca =  c * inv_det;
        const float cb = -b * inv_det;
        const float cc =  a * inv_det;

        const float mid = 0.5f * (a + c);
        const float lam = mid + sqrtf(fmaxf(mid * mid - det, 0.1f));

        if (block0)
            out[3 * IMG_H * IMG_W + j] = (float)((int)ceilf(3.0f * sqrtf(lam)));

        const bool valid = (depth > 0.2f) && (det > 0.0f);
        const float op = opac[j];

        // Exact cull radius^2: alpha < 1/255 guaranteed beyond it.
        float r2 = -1.0f;
        if (valid && op * 255.0f > 1.0f) {
            r2 = 2.0f * lam * __logf(255.0f * op) + 1e-2f;
            if (r2 < 0.0f) r2 = -1.0f;
        }

        // Tile intersection test
        const float cx = fminf(fmaxf(px, tx0), tx1);
        const float cy = fminf(fmaxf(py, ty0), ty1);
        const float ddx = px - cx;
        const float ddy = py - cy;
        if (ddx * ddx + ddy * ddy <= r2) {
            const int p = atomicAdd(&s_cnt, 1);
            sgA[p] = make_float4(px, py, ca, cb);
            sgB[p] = make_float4(cc, op, colors[3 * j + 0], colors[3 * j + 1]);
            sgC[p] = make_float4(colors[3 * j + 2],
                                 1.0f / fmaxf(depth, 1e-6f), 0.0f, 0.0f);
            sdep[p] = depth;
            sidx[p] = j;
        }
    }
    __syncthreads();

    const int cnt = s_cnt;

    // ---- Sort survivors by (depth, original index): stable argsort order.
    // Keys (depth, idx) are unique => rank is a permutation => deterministic.
    for (int e = tid; e < cnt; e += NTHR) {
        const float de = sdep[e];
        const int   ie = sidx[e];
        int rank = 0;
        for (int m = 0; m < cnt; ++m) {
            const float dm = sdep[m];
            rank += (dm < de) || ((dm == de) && (sidx[m] < ie));
        }
        ord[rank] = e;
    }
    __syncthreads();

    // ---- Front-to-back composite ----
    const int x = blockIdx.x * TW + threadIdx.x;
    const int y = blockIdx.y * TH + threadIdx.y;
    const float fx = (float)x;
    const float fy = (float)y;

    float T = 1.0f, aR = 0.0f, aG = 0.0f, aB = 0.0f, aD = 0.0f;

    for (int n = 0; n < cnt; ++n) {
        const int pos = ord[n];
        const float4 A = sgA[pos];
        const float dx = fx - A.x;
        const float dy = fy - A.y;
        const float4 B = sgB[pos];
        const float power = -0.5f * (A.z * dx * dx) - A.w * dx * dy
                            - 0.5f * (B.x * dy * dy);
        if (power > 0.0f) continue;
        const float alpha = fminf(0.99f, B.y * __expf(power));
        if (alpha < (1.0f / 255.0f)) continue;
        const float4 C = sgC[pos];
        const float w = alpha * T;
        aR += w * B.z;
        aG += w * B.w;
        aB += w * C.x;
        aD += w * C.y;
        T *= (1.0f - alpha);
        if (T < 1e-7f) break;
    }

    const int pix = y * IMG_W + x;
    const float m = mask[pix];
    const int HW = IMG_H * IMG_W;
    out[0 * HW + pix] = (aR + T * bg[0]) * m;
    out[1 * HW + pix] = (aG + T * bg[1]) * m;
    out[2 * HW + pix] = (aB + T * bg[2]) * m;
    out[3 * HW + NG + pix] = aD * m;   // invd after color(3*HW) + radii(NG)
}

// ---------------------------------------------------------------------------
extern "C" void kernel_launch(void* const* d_in, const int* in_sizes, int n_in,
                              void* d_out, int out_size)
{
    const float* means3D = (const float*)d_in[0];
    // d_in[1] = means2D (unused by reference math)
    const float* opac    = (const float*)d_in[2];
    const float* colors  = (const float*)d_in[3];
    const float* scales  = (const float*)d_in[4];
    const float* rots    = (const float*)d_in[5];
    const float* view    = (const float*)d_in[6];
    const float* proj    = (const float*)d_in[7];
    const float* bg      = (const float*)d_in[8];
    const float* mask    = (const float*)d_in[9];
    float* out = (float*)d_out;

    dim3 blk(TW, TH);
    dim3 grd(IMG_W / TW, IMG_H / TH);
    fused_kernel<<<grd, blk>>>(means3D, opac, colors, scales, rots,
                               view, proj, bg, mask, out);
}

// round 7
// speedup vs baseline: 6.5621x; 1.1271x over previous
#include <cuda_runtime.h>
#include <math.h>
#include <stdint.h>

#define NG 512
#define IMG_H 256
#define IMG_W 256
#define TW 16
#define TH 8
#define NTHR 128

#define FXC 256.0f
#define FYC 256.0f
#define LIMX (1.3f * 0.5f)
#define LIMY (1.3f * 0.5f)

// ---------------------------------------------------------------------------
// Fully fused: each block = one 16x8 pixel tile. The block preprocesses all
// 512 gaussians itself (4/thread, fully unrolled for ILP), culls against its
// tile with the exact alpha>=1/255 bound, sorts the ~10-30 survivors by
// (depth, index) — reproducing the reference's stable depth argsort among
// contributing gaussians — then composites front-to-back.
// Static smem: 3*512*16 + 512*4*3 + 4 = 30724 B (< 48 KB static cap).
// ---------------------------------------------------------------------------
__global__ void __launch_bounds__(NTHR)
fused_kernel(const float* __restrict__ means3D,
             const float* __restrict__ opac,
             const float* __restrict__ colors,
             const float* __restrict__ scales,
             const float* __restrict__ rots,
             const float* __restrict__ view,
             const float* __restrict__ proj,
             const float* __restrict__ bg,
             const float* __restrict__ mask,
             float* __restrict__ out)
{
    __shared__ float4 sgA[NG];     // survivors: px, py, ca, cb
    __shared__ float4 sgB[NG];     // cc, op, cr, cg
    __shared__ float4 sgC[NG];     // cb(blue), invdepth, -, -
    __shared__ float  sdep[NG];
    __shared__ int    sidx[NG];
    __shared__ int    ord[NG];     // ord[rank] = slot
    __shared__ int    s_cnt;

    const int tid = threadIdx.y * TW + threadIdx.x;
    if (tid == 0) s_cnt = 0;
    __syncthreads();

    const float tx0 = (float)(blockIdx.x * TW);
    const float tx1 = tx0 + (float)(TW - 1);
    const float ty0 = (float)(blockIdx.y * TH);
    const float ty1 = ty0 + (float)(TH - 1);
    const bool block0 = (blockIdx.x == 0) && (blockIdx.y == 0);

    // Broadcast camera constants
    const float V00 = view[0], V01 = view[1], V02 = view[2],  V03 = view[3];
    const float V10 = view[4], V11 = view[5], V12 = view[6],  V13 = view[7];
    const float V20 = view[8], V21 = view[9], V22 = view[10], V23 = view[11];
    const float P00 = proj[0],  P01 = proj[1],  P02 = proj[2],  P03 = proj[3];
    const float P10 = proj[4],  P11 = proj[5],  P12 = proj[6],  P13 = proj[7];
    const float P30 = proj[12], P31 = proj[13], P32 = proj[14], P33 = proj[15];

    // ---- Per-gaussian preprocess + cull (4 gaussians per thread, unrolled
    //      so the 4 independent dependency chains interleave) ----
    #pragma unroll
    for (int k = 0; k < NG / NTHR; ++k) {
        const int j = tid + NTHR * k;

        const float m0 = means3D[3 * j + 0];
        const float m1 = means3D[3 * j + 1];
        const float m2 = means3D[3 * j + 2];

        const float t0 = V00 * m0 + V01 * m1 + V02 * m2 + V03;
        const float t1 = V10 * m0 + V11 * m1 + V12 * m2 + V13;
        const float depth = V20 * m0 + V21 * m1 + V22 * m2 + V23;

        const float c0 = P00 * m0 + P01 * m1 + P02 * m2 + P03;
        const float c1 = P10 * m0 + P11 * m1 + P12 * m2 + P13;
        const float c3 = P30 * m0 + P31 * m1 + P32 * m2 + P33;
        const float pw = __fdividef(1.0f, c3 + 1e-7f);
        const float px = ((c0 * pw + 1.0f) * (float)IMG_W - 1.0f) * 0.5f;
        const float py = ((c1 * pw + 1.0f) * (float)IMG_H - 1.0f) * 0.5f;

        const float4 q = reinterpret_cast<const float4*>(rots)[j];
        float qw = q.x, qx = q.y, qy = q.z, qz = q.w;
        const float qn = rsqrtf(qw * qw + qx * qx + qy * qy + qz * qz);
        qw *= qn; qx *= qn; qy *= qn; qz *= qn;
        const float R00 = 1.0f - 2.0f * (qy * qy + qz * qz);
        const float R01 = 2.0f * (qx * qy - qw * qz);
        const float R02 = 2.0f * (qx * qz + qw * qy);
        const float R10 = 2.0f * (qx * qy + qw * qz);
        const float R11 = 1.0f - 2.0f * (qx * qx + qz * qz);
        const float R12 = 2.0f * (qy * qz - qw * qx);
        const float R20 = 2.0f * (qx * qz - qw * qy);
        const float R21 = 2.0f * (qy * qz + qw * qx);
        const float R22 = 1.0f - 2.0f * (qx * qx + qy * qy);

        const float s0 = scales[3 * j + 0];
        const float s1 = scales[3 * j + 1];
        const float s2 = scales[3 * j + 2];

        const float M00 = R00 * s0, M01 = R01 * s1, M02 = R02 * s2;
        const float M10 = R10 * s0, M11 = R11 * s1, M12 = R12 * s2;
        const float M20 = R20 * s0, M21 = R21 * s1, M22 = R22 * s2;
        const float C00 = M00 * M00 + M01 * M01 + M02 * M02;
        const float C01 = M00 * M10 + M01 * M11 + M02 * M12;
        const float C02 = M00 * M20 + M01 * M21 + M02 * M22;
        const float C11 = M10 * M10 + M11 * M11 + M12 * M12;
        const float C12 = M10 * M20 + M11 * M21 + M12 * M22;
        const float C22 = M20 * M20 + M21 * M21 + M22 * M22;

        const float invz = __fdividef(1.0f, depth);
        const float ttx = fminf(fmaxf(t0 * invz, -LIMX), LIMX) * depth;
        const float tty = fminf(fmaxf(t1 * invz, -LIMY), LIMY) * depth;
        const float J00 = FXC * invz;
        const float J02 = -FXC * ttx * invz * invz;
        const float J11 = FYC * invz;
        const float J12 = -FYC * tty * invz * invz;

        const float T00 = J00 * V00 + J02 * V20;
        const float T01 = J00 * V01 + J02 * V21;
        const float T02 = J00 * V02 + J02 * V22;
        const float T10 = J11 * V10 + J12 * V20;
        const float T11 = J11 * V11 + J12 * V21;
        const float T12 = J11 * V12 + J12 * V22;

        const float u0 = C00 * T00 + C01 * T01 + C02 * T02;
        const float u1 = C01 * T00 + C11 * T01 + C12 * T02;
        const float u2 = C02 * T00 + C12 * T01 + C22 * T02;
        const float w0 = C00 * T10 + C01 * T11 + C02 * T12;
        const float w1 = C01 * T10 + C11 * T11 + C12 * T12;
        const float w2 = C02 * T10 + C12 * T11 + C22 * T12;
        const float a = T00 * u0 + T01 * u1 + T02 * u2 + 0.3f;
        const float b = T10 * u0 + T11 * u1 + T12 * u2;
        const float c = T10 * w0 + T11 * w1 + T12 * w2 + 0.3f;

        const float det = a * c - b * b;
        const float inv_det = __fdividef(1.0f, (det != 0.0f) ? det : 1.0f);
        const float ca =  c * inv_det;
        const float cb = -b * inv_det;
        const float cc =  a * inv_det;

        const float mid = 0.5f * (a + c);
        const float lam = mid + sqrtf(fmaxf(mid * mid - det, 0.1f));

        if (block0)
            out[3 * IMG_H * IMG_W + j] = (float)((int)ceilf(3.0f * sqrtf(lam)));

        const bool valid = (depth > 0.2f) && (det > 0.0f);
        const float op = opac[j];

        // Exact cull radius^2: alpha < 1/255 guaranteed beyond it.
        float r2 = -1.0f;
        if (valid && op * 255.0f > 1.0f) {
            r2 = 2.0f * lam * __logf(255.0f * op) + 1e-2f;
            if (r2 < 0.0f) r2 = -1.0f;
        }

        // Tile intersection test
        const float cx = fminf(fmaxf(px, tx0), tx1);
        const float cy = fminf(fmaxf(py, ty0), ty1);
        const float ddx = px - cx;
        const float ddy = py - cy;
        if (ddx * ddx + ddy * ddy <= r2) {
            const int p = atomicAdd(&s_cnt, 1);
            sgA[p] = make_float4(px, py, ca, cb);
            sgB[p] = make_float4(cc, op, colors[3 * j + 0], colors[3 * j + 1]);
            sgC[p] = make_float4(colors[3 * j + 2],
                                 __fdividef(1.0f, fmaxf(depth, 1e-6f)),
                                 0.0f, 0.0f);
            sdep[p] = depth;
            sidx[p] = j;
        }
    }
    __syncthreads();

    const int cnt = s_cnt;

    // ---- Sort survivors by (depth, original index): stable argsort order.
    // Keys (depth, idx) are unique => rank is a permutation => deterministic.
    for (int e = tid; e < cnt; e += NTHR) {
        const float de = sdep[e];
        const int   ie = sidx[e];
        int rank = 0;
        for (int m = 0; m < cnt; ++m) {
            const float dm = sdep[m];
            rank += (dm < de) || ((dm == de) && (sidx[m] < ie));
        }
        ord[rank] = e;
    }
    __syncthreads();

    // ---- Front-to-back composite ----
    const int x = blockIdx.x * TW + threadIdx.x;
    const int y = blockIdx.y * TH + threadIdx.y;
    const float fx = (float)x;
    const float fy = (float)y;

    float T = 1.0f, aR = 0.0f, aG = 0.0f, aB = 0.0f, aD = 0.0f;

    for (int n = 0; n < cnt; ++n) {
        const int pos = ord[n];
        const float4 A = sgA[pos];
        const float dx = fx - A.x;
        const float dy = fy - A.y;
        const float4 B = sgB[pos];
        const float power = -0.5f * (A.z * dx * dx) - A.w * dx * dy
                            - 0.5f * (B.x * dy * dy);
        if (power > 0.0f) continue;
        const float alpha = fminf(0.99f, B.y * __expf(power));
        if (alpha < (1.0f / 255.0f)) continue;
        const float4 C = sgC[pos];
        const float w = alpha * T;
        aR += w * B.z;
        aG += w * B.w;
        aB += w * C.x;
        aD += w * C.y;
        T *= (1.0f - alpha);
        if (T < 1e-7f) break;
    }

    const int pix = y * IMG_W + x;
    const float m = mask[pix];
    const int HW = IMG_H * IMG_W;
    out[0 * HW + pix] = (aR + T * bg[0]) * m;
    out[1 * HW + pix] = (aG + T * bg[1]) * m;
    out[2 * HW + pix] = (aB + T * bg[2]) * m;
    out[3 * HW + NG + pix] = aD * m;   // invd after color(3*HW) + radii(NG)
}

// ---------------------------------------------------------------------------
extern "C" void kernel_launch(void* const* d_in, const int* in_sizes, int n_in,
                              void* d_out, int out_size)
{
    const float* means3D = (const float*)d_in[0];
    // d_in[1] = means2D (unused by reference math)
    const float* opac    = (const float*)d_in[2];
    const float* colors  = (const float*)d_in[3];
    const float* scales  = (const float*)d_in[4];
    const float* rots    = (const float*)d_in[5];
    const float* view    = (const float*)d_in[6];
    const float* proj    = (const float*)d_in[7];
    const float* bg      = (const float*)d_in[8];
    const float* mask    = (const float*)d_in[9];
    float* out = (float*)d_out;

    dim3 blk(TW, TH);
    dim3 grd(IMG_W / TW, IMG_H / TH);
    fused_kernel<<<grd, blk>>>(means3D, opac, colors, scales, rots,
                               view, proj, bg, mask, out);
}

// round 8
// speedup vs baseline: 6.6753x; 1.0172x over previous
#include <cuda_runtime.h>
#include <math.h>
#include <stdint.h>

#define NG 512
#define IMG_H 256
#define IMG_W 256
#define TW 16
#define TH 8
#define NTHR 128

#define FXC 256.0f
#define FYC 256.0f
#define LIMX (1.3f * 0.5f)
#define LIMY (1.3f * 0.5f)

// Per-gaussian preprocessed data (unsorted, indexed by gaussian id):
//  gA: px, py, ca, cb        gB: cc, op, cr, cg
//  gC: cb(blue), invdepth, depth, r2(cull radius^2; <0 => never visible)
__device__ float4 gA[NG];
__device__ float4 gB[NG];
__device__ float4 gC[NG];

// ---------------------------------------------------------------------------
// Preprocess: one thread per gaussian, spread over 8 SM-resident blocks.
// All the MUFU-heavy math (rcp/rsqrt/sqrt/log) happens exactly once per
// gaussian instead of once per (gaussian, tile).
// ---------------------------------------------------------------------------
__global__ void __launch_bounds__(64)
preprocess_kernel(const float* __restrict__ means3D,
                  const float* __restrict__ opac,
                  const float* __restrict__ colors,
                  const float* __restrict__ scales,
                  const float* __restrict__ rots,
                  const float* __restrict__ view,
                  const float* __restrict__ proj,
                  float* __restrict__ radii_out)
{
    const int j = blockIdx.x * 64 + threadIdx.x;
    if (j >= NG) return;

    const float V00 = view[0], V01 = view[1], V02 = view[2],  V03 = view[3];
    const float V10 = view[4], V11 = view[5], V12 = view[6],  V13 = view[7];
    const float V20 = view[8], V21 = view[9], V22 = view[10], V23 = view[11];

    const float m0 = means3D[3 * j + 0];
    const float m1 = means3D[3 * j + 1];
    const float m2 = means3D[3 * j + 2];

    const float t0 = V00 * m0 + V01 * m1 + V02 * m2 + V03;
    const float t1 = V10 * m0 + V11 * m1 + V12 * m2 + V13;
    const float depth = V20 * m0 + V21 * m1 + V22 * m2 + V23;

    const float c0 = proj[0]  * m0 + proj[1]  * m1 + proj[2]  * m2 + proj[3];
    const float c1 = proj[4]  * m0 + proj[5]  * m1 + proj[6]  * m2 + proj[7];
    const float c3 = proj[12] * m0 + proj[13] * m1 + proj[14] * m2 + proj[15];
    const float pw = __fdividef(1.0f, c3 + 1e-7f);
    const float px = ((c0 * pw + 1.0f) * (float)IMG_W - 1.0f) * 0.5f;
    const float py = ((c1 * pw + 1.0f) * (float)IMG_H - 1.0f) * 0.5f;

    const float4 q = reinterpret_cast<const float4*>(rots)[j];
    float qw = q.x, qx = q.y, qy = q.z, qz = q.w;
    const float qn = rsqrtf(qw * qw + qx * qx + qy * qy + qz * qz);
    qw *= qn; qx *= qn; qy *= qn; qz *= qn;
    const float R00 = 1.0f - 2.0f * (qy * qy + qz * qz);
    const float R01 = 2.0f * (qx * qy - qw * qz);
    const float R02 = 2.0f * (qx * qz + qw * qy);
    const float R10 = 2.0f * (qx * qy + qw * qz);
    const float R11 = 1.0f - 2.0f * (qx * qx + qz * qz);
    const float R12 = 2.0f * (qy * qz - qw * qx);
    const float R20 = 2.0f * (qx * qz - qw * qy);
    const float R21 = 2.0f * (qy * qz + qw * qx);
    const float R22 = 1.0f - 2.0f * (qx * qx + qy * qy);

    const float s0 = scales[3 * j + 0];
    const float s1 = scales[3 * j + 1];
    const float s2 = scales[3 * j + 2];

    const float M00 = R00 * s0, M01 = R01 * s1, M02 = R02 * s2;
    const float M10 = R10 * s0, M11 = R11 * s1, M12 = R12 * s2;
    const float M20 = R20 * s0, M21 = R21 * s1, M22 = R22 * s2;
    const float C00 = M00 * M00 + M01 * M01 + M02 * M02;
    const float C01 = M00 * M10 + M01 * M11 + M02 * M12;
    const float C02 = M00 * M20 + M01 * M21 + M02 * M22;
    const float C11 = M10 * M10 + M11 * M11 + M12 * M12;
    const float C12 = M10 * M20 + M11 * M21 + M12 * M22;
    const float C22 = M20 * M20 + M21 * M21 + M22 * M22;

    const float invz = __fdividef(1.0f, depth);
    const float ttx = fminf(fmaxf(t0 * invz, -LIMX), LIMX) * depth;
    const float tty = fminf(fmaxf(t1 * invz, -LIMY), LIMY) * depth;
    const float J00 = FXC * invz;
    const float J02 = -FXC * ttx * invz * invz;
    const float J11 = FYC * invz;
    const float J12 = -FYC * tty * invz * invz;

    const float T00 = J00 * V00 + J02 * V20;
    const float T01 = J00 * V01 + J02 * V21;
    const float T02 = J00 * V02 + J02 * V22;
    const float T10 = J11 * V10 + J12 * V20;
    const float T11 = J11 * V11 + J12 * V21;
    const float T12 = J11 * V12 + J12 * V22;

    const float u0 = C00 * T00 + C01 * T01 + C02 * T02;
    const float u1 = C01 * T00 + C11 * T01 + C12 * T02;
    const float u2 = C02 * T00 + C12 * T01 + C22 * T02;
    const float w0 = C00 * T10 + C01 * T11 + C02 * T12;
    const float w1 = C01 * T10 + C11 * T11 + C12 * T12;
    const float w2 = C02 * T10 + C12 * T11 + C22 * T12;
    const float a = T00 * u0 + T01 * u1 + T02 * u2 + 0.3f;
    const float b = T10 * u0 + T11 * u1 + T12 * u2;
    const float c = T10 * w0 + T11 * w1 + T12 * w2 + 0.3f;

    const float det = a * c - b * b;
    const float inv_det = __fdividef(1.0f, (det != 0.0f) ? det : 1.0f);
    const float ca =  c * inv_det;
    const float cb = -b * inv_det;
    const float cc =  a * inv_det;

    const float mid = 0.5f * (a + c);
    const float lam = mid + sqrtf(fmaxf(mid * mid - det, 0.1f));

    radii_out[j] = (float)((int)ceilf(3.0f * sqrtf(lam)));

    const bool valid = (depth > 0.2f) && (det > 0.0f);
    const float op = opac[j];

    // Exact cull radius^2: alpha < 1/255 guaranteed beyond it.
    float r2 = -1.0f;
    if (valid && op * 255.0f > 1.0f) {
        r2 = 2.0f * lam * __logf(255.0f * op) + 1e-2f;
        if (r2 < 0.0f) r2 = -1.0f;
    }

    gA[j] = make_float4(px, py, ca, cb);
    gB[j] = make_float4(cc, op, colors[3 * j + 0], colors[3 * j + 1]);
    gC[j] = make_float4(colors[3 * j + 2],
                        __fdividef(1.0f, fmaxf(depth, 1e-6f)),
                        depth, r2);
}

// ---------------------------------------------------------------------------
// Raster: each block = one 16x8 tile. Cull all 512 gaussians (pure ALU/FMA,
// L2-broadcast loads), ballot-compact survivors into smem (id order), rank-
// sort the ~10-30 survivors by (depth, id) — the reference's stable depth
// argsort among contributors — then composite front-to-back.
// ---------------------------------------------------------------------------
__global__ void __launch_bounds__(NTHR)
raster_kernel(const float* __restrict__ bg,
              const float* __restrict__ mask,
              float* __restrict__ out)
{
    __shared__ float4 ssA[NG];
    __shared__ float4 ssB[NG];
    __shared__ float4 ssC[NG];
    __shared__ int    ord[NG];
    __shared__ uint32_t bm[NG / 32];
    __shared__ int wpre[NG / 32 + 1];

    const int tid  = threadIdx.y * TW + threadIdx.x;
    const int warp = tid >> 5;
    const int lane = tid & 31;

    const float tx0 = (float)(blockIdx.x * TW);
    const float tx1 = tx0 + (float)(TW - 1);
    const float ty0 = (float)(blockIdx.y * TH);
    const float ty1 = ty0 + (float)(TH - 1);

    // Phase 1: cull. j = k*128 + warp*32 + lane -> word index k*4 + warp.
    #pragma unroll
    for (int k = 0; k < NG / NTHR; ++k) {
        const int j = k * NTHR + tid;
        const float4 A = gA[j];
        const float r2 = gC[j].w;
        const float cx = fminf(fmaxf(A.x, tx0), tx1);
        const float cy = fminf(fmaxf(A.y, ty0), ty1);
        const float ddx = A.x - cx;
        const float ddy = A.y - cy;
        const uint32_t bal = __ballot_sync(0xFFFFFFFFu,
                                           ddx * ddx + ddy * ddy <= r2);
        if (lane == 0) bm[k * 4 + warp] = bal;
    }
    __syncthreads();

    if (tid == 0) {
        int acc = 0;
        #pragma unroll
        for (int k = 0; k < NG / 32; ++k) { wpre[k] = acc; acc += __popc(bm[k]); }
        wpre[NG / 32] = acc;
    }
    __syncthreads();

    // Phase 2: compaction (preserves gaussian-id order)
    #pragma unroll
    for (int k = 0; k < NG / NTHR; ++k) {
        const int j = k * NTHR + tid;
        const uint32_t w = bm[j >> 5];
        const uint32_t bit = 1u << (j & 31);
        if (w & bit) {
            const int pos = wpre[j >> 5] + __popc(w & (bit - 1u));
            ssA[pos] = gA[j];
            ssB[pos] = gB[j];
            ssC[pos] = gC[j];
        }
    }
    __syncthreads();
    const int cnt = wpre[NG / 32];

    // Phase 3: rank-sort survivors by (depth, id). Slots are in id order, so
    // the tie-break on id is the slot index. Unique keys => deterministic.
    for (int e = tid; e < cnt; e += NTHR) {
        const float de = ssC[e].z;
        int rank = 0;
        for (int m = 0; m < cnt; ++m) {
            const float dm = ssC[m].z;
            rank += (dm < de) || ((dm == de) && (m < e));
        }
        ord[rank] = e;
    }
    __syncthreads();

    // Phase 4: front-to-back composite
    const int x = blockIdx.x * TW + threadIdx.x;
    const int y = blockIdx.y * TH + threadIdx.y;
    const float fx = (float)x;
    const float fy = (float)y;

    float T = 1.0f, aR = 0.0f, aG = 0.0f, aB = 0.0f, aD = 0.0f;

    for (int n = 0; n < cnt; ++n) {
        const int pos = ord[n];
        const float4 A = ssA[pos];
        const float dx = fx - A.x;
        const float dy = fy - A.y;
        const float4 B = ssB[pos];
        const float power = -0.5f * (A.z * dx * dx) - A.w * dx * dy
                            - 0.5f * (B.x * dy * dy);
        if (power > 0.0f) continue;
        const float alpha = fminf(0.99f, B.y * __expf(power));
        if (alpha < (1.0f / 255.0f)) continue;
        const float4 C = ssC[pos];
        const float w = alpha * T;
        aR += w * B.z;
        aG += w * B.w;
        aB += w * C.x;
        aD += w * C.y;
        T *= (1.0f - alpha);
        if (T < 1e-7f) break;
    }

    const int pix = y * IMG_W + x;
    const float m = mask[pix];
    const int HW = IMG_H * IMG_W;
    out[0 * HW + pix] = (aR + T * bg[0]) * m;
    out[1 * HW + pix] = (aG + T * bg[1]) * m;
    out[2 * HW + pix] = (aB + T * bg[2]) * m;
    out[3 * HW + NG + pix] = aD * m;   // invd after color(3*HW) + radii(NG)
}

// ---------------------------------------------------------------------------
extern "C" void kernel_launch(void* const* d_in, const int* in_sizes, int n_in,
                              void* d_out, int out_size)
{
    const float* means3D = (const float*)d_in[0];
    // d_in[1] = means2D (unused by reference math)
    const float* opac    = (const float*)d_in[2];
    const float* colors  = (const float*)d_in[3];
    const float* scales  = (const float*)d_in[4];
    const float* rots    = (const float*)d_in[5];
    const float* view    = (const float*)d_in[6];
    const float* proj    = (const float*)d_in[7];
    const float* bg      = (const float*)d_in[8];
    const float* mask    = (const float*)d_in[9];
    float* out = (float*)d_out;

    float* radii_out = out + 3 * IMG_H * IMG_W;

    preprocess_kernel<<<8, 64>>>(means3D, opac, colors, scales, rots,
                                 view, proj, radii_out);

    dim3 blk(TW, TH);
    dim3 grd(IMG_W / TW, IMG_H / TH);
    raster_kernel<<<grd, blk>>>(bg, mask, out);
}